// round 16
// baseline (speedup 1.0000x reference)
#include <cuda_runtime.h>
#include <cuda_fp16.h>
#include <cstdint>

#define BATCH 256
#define TSEQ  512
#define HID   512
#define FUT   64
#define NCTA  256
#define NTHR  256
#define MB    32                   // batch rows per CTA
#define UH    16                   // hidden units per CTA slice
#define KC    128                  // K chunk (halfs)
#define CP    136                  // chunk row pitch (halfs); 68 words/row -> conflict-free
#define ABUF  (32 * CP)            // A staging buffer: 32 rows (4352 halfs)
#define BBUF  (64 * CP)            // B staging buffer: 64 gate rows (8704 halfs)
#define SHC_PITCH 68
#define SMEM_BYTES ((2 * ABUF + 2 * BBUF) * 2 + 32 * SHC_PITCH * 4)   // 60,928 B

// ---------------- persistent device state ----------------
__device__ __half g_h0[2][BATCH * HID];
__device__ __half g_h1[2][BATCH * HID];
__device__ float  g_c0[BATCH * HID];
__device__ float  g_c1[BATCH * HID];
__device__ float  g_o[BATCH];
__device__ unsigned g_arrive;
__device__ unsigned g_release;
// fp16 weights: 0=w_hh0 1=w_ih1 2=w_hh1 3=pw_hh0 4=pw_ih1 5=pw_hh1
__device__ __half g_wh[6][4 * HID * HID];

// ---------------- helpers ----------------
__device__ __forceinline__ void cp16(void* dst_smem, const void* src_gmem) {
    unsigned d = (unsigned)__cvta_generic_to_shared(dst_smem);
    asm volatile("cp.async.cg.shared.global [%0], [%1], 16;" :: "r"(d), "l"(src_gmem));
}
__device__ __forceinline__ void cp_commit() { asm volatile("cp.async.commit_group;"); }

__device__ __forceinline__ float sgm(float x) { return 1.0f / (1.0f + expf(-x)); }

__device__ __forceinline__ void sthcg(__half* p, float v) {
    __half h = __float2half_rn(v);
    unsigned short u = *(unsigned short*)&h;
    asm volatile("st.global.cg.u16 [%0], %1;" :: "l"(p), "h"(u));
}
__device__ __forceinline__ float ldhcg(const __half* p) {
    unsigned short u;
    asm volatile("ld.global.cg.u16 %0, [%1];" : "=h"(u) : "l"(p));
    __half h = *(__half*)&u;
    return __half2float(h);
}

// grid-wide barrier (monotonic; reset by init kernel each launch)
__device__ __forceinline__ void gbar(unsigned& gen) {
    gen++;
    __syncthreads();
    if (threadIdx.x == 0) {
        __threadfence();
        unsigned a = atomicAdd(&g_arrive, 1u) + 1u;
        if (a == (unsigned)NCTA * gen) {
            atomicExch(&g_release, gen);
        } else {
            while (*((volatile unsigned*)&g_release) < gen) { __nanosleep(32); }
        }
        __threadfence();
    }
    __syncthreads();
}

__device__ __forceinline__ void mma16(float* c, uint32_t a0, uint32_t a1, uint32_t a2, uint32_t a3,
                                      uint32_t b0, uint32_t b1) {
    asm volatile(
        "mma.sync.aligned.m16n8k16.row.col.f32.f16.f16.f32 "
        "{%0,%1,%2,%3},{%4,%5,%6,%7},{%8,%9},{%0,%1,%2,%3};"
        : "+f"(c[0]), "+f"(c[1]), "+f"(c[2]), "+f"(c[3])
        : "r"(a0), "r"(a1), "r"(a2), "r"(a3), "r"(b0), "r"(b1));
}

__device__ __forceinline__ void ldsm4(uint32_t& r0, uint32_t& r1, uint32_t& r2, uint32_t& r3,
                                      uint32_t addr) {
    asm volatile("ldmatrix.sync.aligned.m8n8.x4.shared.b16 {%0,%1,%2,%3}, [%4];"
                 : "=r"(r0), "=r"(r1), "=r"(r2), "=r"(r3) : "r"(addr));
}

// stage one K-chunk: A = 32 h rows, B = 64 gate rows (4 gates x 16 units)
__device__ __forceinline__ void stage_ab(__half* dstA, __half* dstB,
                                         const __half* hsrc, const __half* Wsrc,
                                         int u0, int kc0, int tid) {
#pragma unroll
    for (int i = 0; i < 2; i++) {
        int idx = tid + i * NTHR;       // 512 x 16B
        int r = idx >> 4, c8 = idx & 15;
        cp16(dstA + r * CP + c8 * 8, hsrc + (size_t)r * HID + kc0 + c8 * 8);
    }
#pragma unroll
    for (int i = 0; i < 4; i++) {
        int idx = tid + i * NTHR;       // 1024 x 16B
        int r = idx >> 4, c8 = idx & 15;
        int q = r >> 4, j = r & 15;     // smem row r = q*16+j  <-> W row q*HID+u0+j
        cp16(dstB + r * CP + c8 * 8, Wsrc + (size_t)(q * HID + u0 + j) * HID + kc0 + c8 * 8);
    }
    cp_commit();
}

// one K=512 GEMM: cfr += h[32xK] @ Wslice[64xK]^T  (fp16 HMMA; ldmatrix-fed, m16n16 warp tile)
__device__ __forceinline__ void gemm16(float (&cfr)[2][4], const __half* hsrc,
                                       const __half* Wsrc, int u0,
                                       __half* shA, __half* shB,
                                       int tid, uint32_t aAddr0, uint32_t bAddr0) {
    stage_ab(shA, shB, hsrc, Wsrc, u0, 0, tid);
    stage_ab(shA + ABUF, shB + BBUF, hsrc, Wsrc, u0, KC, tid);
#pragma unroll 1
    for (int ch = 0; ch < 4; ch++) {
        if (ch < 3) asm volatile("cp.async.wait_group 1;");
        else        asm volatile("cp.async.wait_group 0;");
        __syncthreads();
        const uint32_t Ab = aAddr0 + (uint32_t)(ch & 1) * (ABUF * 2);
        const uint32_t Bb = bAddr0 + (uint32_t)(ch & 1) * (BBUF * 2);
#pragma unroll
        for (int k16 = 0; k16 < KC / 16; k16++) {
            uint32_t kb = (uint32_t)k16 * 32;        // 16 halfs = 32 B
            uint32_t a0, a1, a2, a3, b0, b1, b2, b3;
            ldsm4(a0, a1, a2, a3, Ab + kb);          // A m16k16 tile
            ldsm4(b0, b1, b2, b3, Bb + kb);          // both n8 tiles
            mma16(cfr[0], a0, a1, a2, a3, b0, b1);
            mma16(cfr[1], a0, a1, a2, a3, b2, b3);
        }
        __syncthreads();
        if (ch + 2 < 4)
            stage_ab(shA + (ch & 1) * ABUF, shB + (ch & 1) * BBUF, hsrc, Wsrc, u0,
                     (ch + 2) * KC, tid);
    }
}

__device__ __forceinline__ void zero_c(float (&cfr)[2][4]) {
#pragma unroll
    for (int ns = 0; ns < 2; ns++)
#pragma unroll
        for (int r = 0; r < 4; r++) cfr[ns][r] = 0.0f;
}

// scatter C frags to shC[batch][gate_row]; C frag: c0,c1=(row g, col 2t,2t+1), c2,c3=row g+8
__device__ __forceinline__ void dump_c(const float (&cfr)[2][4], float* shC,
                                       int wm, int wn, int gid, int tid4) {
#pragma unroll
    for (int ns = 0; ns < 2; ns++) {
        int row = wm * 16 + gid;
        int col = wn * 16 + ns * 8 + 2 * tid4;
        *(float2*)(shC + row * SHC_PITCH + col)       = make_float2(cfr[ns][0], cfr[ns][1]);
        *(float2*)(shC + (row + 8) * SHC_PITCH + col) = make_float2(cfr[ns][2], cfr[ns][3]);
    }
}

// pointwise LSTM update; thread owns unit jj, 2 batch rows. h stored fp16.
__device__ __forceinline__ void cell_update(const float* shC, const float bs[4],
                                            const float* xinv, const float xw[4],
                                            float* cbuf, __half* hout,
                                            int b0, int bq, int jj, int ju) {
#pragma unroll
    for (int i = 0; i < 2; i++) {
        int bb = bq * 2 + i;
        float pi = shC[bb * SHC_PITCH +  0 + jj] + bs[0];
        float pf = shC[bb * SHC_PITCH + 16 + jj] + bs[1];
        float pg = shC[bb * SHC_PITCH + 32 + jj] + bs[2];
        float po = shC[bb * SHC_PITCH + 48 + jj] + bs[3];
        if (xinv) {
            float xv = xinv[i];
            pi += xv * xw[0]; pf += xv * xw[1]; pg += xv * xw[2]; po += xv * xw[3];
        }
        size_t idx = (size_t)(b0 + bb) * HID + ju;
        float cc = sgm(pf) * cbuf[idx] + sgm(pi) * tanhf(pg);
        cbuf[idx] = cc;
        sthcg(hout + idx, sgm(po) * tanhf(cc));
    }
}

// out[:, s] = hbuf @ wvec + bias ; stashes g_o. Simple scalar fp16 reads.
__device__ __forceinline__ void head_dot(const __half* hbuf, const float* wvec, const float* bias,
                                         float* out, int s, int b0, int tid) {
    int warp = tid >> 5, lane = tid & 31;
    float bv = __ldg(bias);
    for (int bb = warp; bb < MB; bb += 8) {
        int b = b0 + bb;
        float acc = 0.0f;
        for (int k = lane; k < HID; k += 32)
            acc += ldhcg(hbuf + (size_t)b * HID + k) * __ldg(wvec + k);
#pragma unroll
        for (int off = 16; off; off >>= 1) acc += __shfl_xor_sync(0xffffffffu, acc, off);
        if (lane == 0) {
            float o = acc + bv;
            out[b * FUT + s] = o;
            g_o[b] = o;
        }
    }
}

// ---------------- kernels ----------------
__global__ void init_kernel(const float* w0, const float* w1, const float* w2,
                            const float* w3, const float* w4, const float* w5) {
    const float* src[6] = {w0, w1, w2, w3, w4, w5};
    size_t i0 = blockIdx.x * (size_t)blockDim.x + threadIdx.x;
    size_t stride = (size_t)gridDim.x * blockDim.x;
    const size_t WN = (size_t)4 * HID * HID;
#pragma unroll 1
    for (int m = 0; m < 6; m++) {
        const float* s = src[m];
        __half* d = g_wh[m];
        for (size_t i = i0; i < WN; i += stride) d[i] = __float2half_rn(s[i]);
    }
    size_t n = (size_t)BATCH * HID;
    __half hz = __float2half_rn(0.0f);
    for (size_t k = i0; k < n; k += stride) {
        g_h0[0][k] = hz; g_h0[1][k] = hz;
        g_h1[0][k] = hz; g_h1[1][k] = hz;
        g_c0[k] = 0.f;   g_c1[k] = 0.f;
    }
    if (i0 == 0) { g_arrive = 0u; g_release = 0u; }
}

__global__ void __launch_bounds__(NTHR, 2)
lstm_kernel(const float* __restrict__ x,
            const float* __restrict__ w_ih0,
            const float* __restrict__ b_ih0, const float* __restrict__ b_hh0,
            const float* __restrict__ b_ih1, const float* __restrict__ b_hh1,
            const float* __restrict__ fc_w,  const float* __restrict__ fc_b,
            const float* __restrict__ pw_ih0,
            const float* __restrict__ pb_ih0, const float* __restrict__ pb_hh0,
            const float* __restrict__ pb_ih1, const float* __restrict__ pb_hh1,
            const float* __restrict__ pfc_w,  const float* __restrict__ pfc_b,
            float* __restrict__ out) {
    extern __shared__ __half smemh[];
    __half* shA = smemh;                                  // 2 x ABUF
    __half* shB = smemh + 2 * ABUF;                       // 2 x BBUF
    float*  shC = (float*)(smemh + 2 * ABUF + 2 * BBUF);  // 32 x SHC_PITCH floats

    const int tid  = threadIdx.x;
    const int lane = tid & 31;
    const int bt   = blockIdx.x & 7;           // 8 batch tiles of 32
    const int sl   = blockIdx.x >> 3;          // 32 hidden slices of 16
    const int b0   = bt * MB;
    const int u0   = sl * UH;
    const int wid  = tid >> 5;
    const int wm   = wid & 1;                  // batch half (16 rows)
    const int wn   = wid >> 1;                 // gate quarter (16 cols)
    const int gid  = lane >> 2;
    const int tid4 = lane & 3;
    const int jj   = tid & 15;
    const int bq   = tid >> 4;
    const int ju   = u0 + jj;

    // ldmatrix per-lane base addresses (bytes, shared space) — R13 formulas, A base wm*16
    const uint32_t shA_u = (uint32_t)__cvta_generic_to_shared(shA);
    const uint32_t shB_u = (uint32_t)__cvta_generic_to_shared(shB);
    const int r8 = lane & 7;
    const uint32_t aAddr0 = shA_u +
        (uint32_t)(((wm * 16 + ((lane >> 3) & 1) * 8 + r8) * CP + (lane >> 4) * 8) * 2);
    const uint32_t bAddr0 = shB_u +
        (uint32_t)(((wn * 16 + (lane >> 4) * 8 + r8) * CP + ((lane >> 3) & 1) * 8) * 2);

    float bs0[4], bs1[4], pbs0[4], pbs1[4], wi0[4], pwi0[4];
#pragma unroll
    for (int q = 0; q < 4; q++) {
        int r = q * HID + ju;
        bs0[q]  = __ldg(b_ih0 + r)  + __ldg(b_hh0 + r);
        bs1[q]  = __ldg(b_ih1 + r)  + __ldg(b_hh1 + r);
        pbs0[q] = __ldg(pb_ih0 + r) + __ldg(pb_hh0 + r);
        pbs1[q] = __ldg(pb_ih1 + r) + __ldg(pb_hh1 + r);
        wi0[q]  = __ldg(w_ih0 + r);
        pwi0[q] = __ldg(pw_ih0 + r);
    }

    unsigned gen = 0;
    int p = 0;
    float cfr[2][4];

    // ---------------- warmup over observed sequence ----------------
    for (int t = 0; t < TSEQ; t++) {
        gbar(gen);
        // layer 0
        zero_c(cfr);
        gemm16(cfr, g_h0[p] + (size_t)b0 * HID, g_wh[0], u0, shA, shB, tid, aAddr0, bAddr0);
        dump_c(cfr, shC, wm, wn, gid, tid4);
        __syncthreads();
        {
            float xin[2];
#pragma unroll
            for (int i = 0; i < 2; i++)
                xin[i] = __ldg(x + (size_t)(b0 + bq * 2 + i) * TSEQ + t);
            cell_update(shC, bs0, xin, wi0, g_c0, g_h0[p ^ 1], b0, bq, jj, ju);
        }
        gbar(gen);
        // layer 1 (two GEMMs accumulate)
        zero_c(cfr);
        gemm16(cfr, g_h0[p ^ 1] + (size_t)b0 * HID, g_wh[1], u0, shA, shB, tid, aAddr0, bAddr0);
        gemm16(cfr, g_h1[p]     + (size_t)b0 * HID, g_wh[2], u0, shA, shB, tid, aAddr0, bAddr0);
        dump_c(cfr, shC, wm, wn, gid, tid4);
        __syncthreads();
        cell_update(shC, bs1, (const float*)0, bs1 /*unused*/, g_c1, g_h1[p ^ 1], b0, bq, jj, ju);
        p ^= 1;
    }

    gbar(gen);
    if (sl == 0) head_dot(g_h1[p], fc_w, fc_b, out, 0, b0, tid);

    // ---------------- autoregressive prediction ----------------
    for (int s = 1; s < FUT; s++) {
        gbar(gen);
        // pred layer 0
        zero_c(cfr);
        gemm16(cfr, g_h0[p] + (size_t)b0 * HID, g_wh[3], u0, shA, shB, tid, aAddr0, bAddr0);
        dump_c(cfr, shC, wm, wn, gid, tid4);
        __syncthreads();
        {
            float xin[2];
#pragma unroll
            for (int i = 0; i < 2; i++)
                xin[i] = __ldcg(&g_o[b0 + bq * 2 + i]);
            cell_update(shC, pbs0, xin, pwi0, g_c0, g_h0[p ^ 1], b0, bq, jj, ju);
        }
        gbar(gen);
        // pred layer 1
        zero_c(cfr);
        gemm16(cfr, g_h0[p ^ 1] + (size_t)b0 * HID, g_wh[4], u0, shA, shB, tid, aAddr0, bAddr0);
        gemm16(cfr, g_h1[p]     + (size_t)b0 * HID, g_wh[5], u0, shA, shB, tid, aAddr0, bAddr0);
        dump_c(cfr, shC, wm, wn, gid, tid4);
        __syncthreads();
        cell_update(shC, pbs1, (const float*)0, pbs1 /*unused*/, g_c1, g_h1[p ^ 1], b0, bq, jj, ju);
        gbar(gen);
        if (sl == 0) head_dot(g_h1[p ^ 1], pfc_w, pfc_b, out, s, b0, tid);
        p ^= 1;
    }
}

// ---------------- launch ----------------
extern "C" void kernel_launch(void* const* d_in, const int* in_sizes, int n_in,
                              void* d_out, int out_size) {
    (void)in_sizes; (void)n_in; (void)out_size;
    cudaFuncSetAttribute(lstm_kernel, cudaFuncAttributeMaxDynamicSharedMemorySize, SMEM_BYTES);

    const float* x      = (const float*)d_in[0];
    // d_in[1] = future (scalar) — fixed shapes, FUT hardcoded
    const float* w_ih0  = (const float*)d_in[2];
    const float* w_hh0  = (const float*)d_in[3];
    const float* b_ih0  = (const float*)d_in[4];
    const float* b_hh0  = (const float*)d_in[5];
    const float* w_ih1  = (const float*)d_in[6];
    const float* w_hh1  = (const float*)d_in[7];
    const float* b_ih1  = (const float*)d_in[8];
    const float* b_hh1  = (const float*)d_in[9];
    const float* fc_w   = (const float*)d_in[10];
    const float* fc_b   = (const float*)d_in[11];
    const float* pw_ih0 = (const float*)d_in[12];
    const float* pw_hh0 = (const float*)d_in[13];
    const float* pb_ih0 = (const float*)d_in[14];
    const float* pb_hh0 = (const float*)d_in[15];
    const float* pw_ih1 = (const float*)d_in[16];
    const float* pw_hh1 = (const float*)d_in[17];
    const float* pb_ih1 = (const float*)d_in[18];
    const float* pb_hh1 = (const float*)d_in[19];
    const float* pfc_w  = (const float*)d_in[20];
    const float* pfc_b  = (const float*)d_in[21];

    // fp16 weight conversion + state zero + barrier reset
    init_kernel<<<1024, 256>>>(w_hh0, w_ih1, w_hh1, pw_hh0, pw_ih1, pw_hh1);

    lstm_kernel<<<NCTA, NTHR, SMEM_BYTES>>>(
        x, w_ih0, b_ih0, b_hh0, b_ih1, b_hh1, fc_w, fc_b,
        pw_ih0, pb_ih0, pb_hh0, pb_ih1, pb_hh1, pfc_w, pfc_b, (float*)d_out);
}